// round 3
// baseline (speedup 1.0000x reference)
#include <cuda_runtime.h>
#include <cuda_bf16.h>
#include <cstdint>

#define Dh   2048
#define SEQ  1024
#define GRP  2
#define NEXP 8
#define TOPK 2
#define NTOK (GRP*SEQ)          // 2048 tokens
#define NASSIGN (NTOK*TOPK)     // 4096 routed assignments
#define NSLOT (NASSIGN + NTOK)  // 6144 rows total (routed + shared)
#define BM 128
#define BN 128
#define BK 16
#define AST 24                  // smem row stride in bf16 elems (skewed)

// ---------------- device scratch (static: no runtime allocation) ----------------
__device__ int g_counts[NEXP];
__device__ int g_offsets[NEXP];
__device__ int g_cursor[NEXP];
__device__ int g_rowmap[NASSIGN];    // slot -> token id
__device__ int g_slotmap[NASSIGN];   // assignment (t*2+k) -> slot
__device__ __nv_bfloat16 g_act_hi[(size_t)NSLOT * Dh];
__device__ __nv_bfloat16 g_act_lo[(size_t)NSLOT * Dh];
__device__ float g_ys[(size_t)NSLOT * Dh];

// ---------------- routing (indices are INT32: jax silently downgrades int64) ----------------
__global__ void route_zero_kernel() {
    int t = threadIdx.x;
    if (t < NEXP) { g_counts[t] = 0; g_cursor[t] = 0; }
}
__global__ void route_count_kernel(const int* __restrict__ idx) {
    int i = blockIdx.x * blockDim.x + threadIdx.x;
    if (i < NASSIGN) {
        int e = idx[i];
        if (e >= 0 && e < NEXP) atomicAdd(&g_counts[e], 1);
    }
}
__global__ void route_offsets_kernel() {
    if (threadIdx.x == 0) {
        int acc = 0;
        for (int e = 0; e < NEXP; e++) { g_offsets[e] = acc; acc += g_counts[e]; }
    }
}
__global__ void route_scatter_kernel(const int* __restrict__ idx) {
    int i = blockIdx.x * blockDim.x + threadIdx.x;
    if (i < NASSIGN) {
        int e = idx[i];
        if (e < 0) e = 0;
        if (e >= NEXP) e = NEXP - 1;
        int pos = g_offsets[e] + atomicAdd(&g_cursor[e], 1);
        g_rowmap[pos] = i >> 1;   // token id (TOPK=2)
        g_slotmap[i] = pos;
    }
}

// ---------------- mma helpers ----------------
__device__ __forceinline__ void mma_bf16(float c[4], const unsigned a[4], const unsigned b[2]) {
    asm volatile(
        "mma.sync.aligned.m16n8k16.row.col.f32.bf16.bf16.f32 "
        "{%0,%1,%2,%3},{%4,%5,%6,%7},{%8,%9},{%0,%1,%2,%3};\n"
        : "+f"(c[0]), "+f"(c[1]), "+f"(c[2]), "+f"(c[3])
        : "r"(a[0]), "r"(a[1]), "r"(a[2]), "r"(a[3]), "r"(b[0]), "r"(b[1]));
}
__device__ __forceinline__ unsigned pk(__nv_bfloat16 lo, __nv_bfloat16 hi) {
    unsigned a = (unsigned)__bfloat16_as_ushort(lo);
    unsigned b = (unsigned)__bfloat16_as_ushort(hi);
    return a | (b << 16);
}
// split fp32 -> (hi, lo) bf16
__device__ __forceinline__ void split_bf16(float v, __nv_bfloat16& h, __nv_bfloat16& l) {
    h = __float2bfloat16(v);
    l = __float2bfloat16(v - __bfloat162float(h));
}

// ---------------- K1: gate/up GEMMs + SiLU, write act hi/lo ----------------
__global__ void __launch_bounds__(256) moe_k1(
    const float* __restrict__ x,
    const float* __restrict__ gate_w, const float* __restrict__ up_w,
    const float* __restrict__ sgw, const float* __restrict__ suw)
{
    const int seg = blockIdx.z;
    const int cnt = (seg == NEXP) ? NTOK : g_counts[seg];
    const int mtile = blockIdx.y;
    if (mtile * BM >= cnt) return;
    const int ntile = blockIdx.x;
    const int segbase = (seg == NEXP) ? NASSIGN : g_offsets[seg];
    const float* gw = (seg == NEXP) ? sgw : gate_w + (size_t)seg * Dh * Dh;
    const float* uw = (seg == NEXP) ? suw : up_w + (size_t)seg * Dh * Dh;

    __shared__ __align__(16) __nv_bfloat16 sAh[BM * AST], sAl[BM * AST];
    __shared__ __align__(16) __nv_bfloat16 sGh[BN * AST], sGl[BN * AST];
    __shared__ __align__(16) __nv_bfloat16 sUh[BN * AST], sUl[BN * AST];
    __shared__ int stok[BM];

    const int tid = threadIdx.x;
    if (tid < BM) {
        int r = mtile * BM + tid;
        stok[tid] = (r < cnt) ? ((seg == NEXP) ? r : g_rowmap[segbase + r]) : -1;
    }
    __syncthreads();

    const int wid = tid >> 5, lane = tid & 31, gid = lane >> 2, tg = lane & 3;
    const int wm = wid >> 1, wn = wid & 1;

    float accg[2][8][4], accu[2][8][4];
#pragma unroll
    for (int mi = 0; mi < 2; mi++)
#pragma unroll
        for (int ni = 0; ni < 8; ni++)
#pragma unroll
            for (int j = 0; j < 4; j++) { accg[mi][ni][j] = 0.f; accu[mi][ni][j] = 0.f; }

    for (int k0 = 0; k0 < Dh; k0 += BK) {
        // ---- global loads into regs ----
        float4 av[2];
#pragma unroll
        for (int i = 0; i < 2; i++) {
            int a = tid + i * 256; int row = a >> 2, c4 = a & 3;
            int tok = stok[row];
            if (tok >= 0) av[i] = *(const float4*)(x + (size_t)tok * Dh + k0 + c4 * 4);
            else av[i] = make_float4(0.f, 0.f, 0.f, 0.f);
        }
        float4 bv[4];
#pragma unroll
        for (int i = 0; i < 4; i++) {
            int b = tid + i * 256; int mat = b >> 9; int row = (b >> 2) & 127; int c4 = b & 3;
            const float* W = mat ? uw : gw;
            bv[i] = *(const float4*)(W + (size_t)(ntile * BN + row) * Dh + k0 + c4 * 4);
        }
        __syncthreads();   // previous iter's MMA reads done
        // ---- split + STS ----
#pragma unroll
        for (int i = 0; i < 2; i++) {
            int a = tid + i * 256; int row = a >> 2, c4 = a & 3;
            __nv_bfloat16 h0, l0, h1, l1, h2, l2, h3, l3;
            split_bf16(av[i].x, h0, l0); split_bf16(av[i].y, h1, l1);
            split_bf16(av[i].z, h2, l2); split_bf16(av[i].w, h3, l3);
            *(uint2*)&sAh[row * AST + c4 * 4] = make_uint2(pk(h0, h1), pk(h2, h3));
            *(uint2*)&sAl[row * AST + c4 * 4] = make_uint2(pk(l0, l1), pk(l2, l3));
        }
#pragma unroll
        for (int i = 0; i < 4; i++) {
            int b = tid + i * 256; int mat = b >> 9; int row = (b >> 2) & 127; int c4 = b & 3;
            __nv_bfloat16 h0, l0, h1, l1, h2, l2, h3, l3;
            split_bf16(bv[i].x, h0, l0); split_bf16(bv[i].y, h1, l1);
            split_bf16(bv[i].z, h2, l2); split_bf16(bv[i].w, h3, l3);
            __nv_bfloat16* dsth = mat ? sUh : sGh;
            __nv_bfloat16* dstl = mat ? sUl : sGl;
            *(uint2*)&dsth[row * AST + c4 * 4] = make_uint2(pk(h0, h1), pk(h2, h3));
            *(uint2*)&dstl[row * AST + c4 * 4] = make_uint2(pk(l0, l1), pk(l2, l3));
        }
        __syncthreads();

        // ---- fragments + MMA ----
        unsigned ah[2][4], al[2][4];
#pragma unroll
        for (int mi = 0; mi < 2; mi++) {
            int mb = wm * 32 + mi * 16;
            int r0 = mb + gid, r1 = mb + gid + 8, kc = tg * 2;
            ah[mi][0] = *(const unsigned*)&sAh[r0 * AST + kc];
            ah[mi][1] = *(const unsigned*)&sAh[r1 * AST + kc];
            ah[mi][2] = *(const unsigned*)&sAh[r0 * AST + kc + 8];
            ah[mi][3] = *(const unsigned*)&sAh[r1 * AST + kc + 8];
            al[mi][0] = *(const unsigned*)&sAl[r0 * AST + kc];
            al[mi][1] = *(const unsigned*)&sAl[r1 * AST + kc];
            al[mi][2] = *(const unsigned*)&sAl[r0 * AST + kc + 8];
            al[mi][3] = *(const unsigned*)&sAl[r1 * AST + kc + 8];
        }
#pragma unroll
        for (int ni = 0; ni < 8; ni++) {
            int n = wn * 64 + ni * 8 + gid;
            unsigned bgh[2], bgl[2], buh[2], bul[2];
            bgh[0] = *(const unsigned*)&sGh[n * AST + tg * 2];
            bgh[1] = *(const unsigned*)&sGh[n * AST + tg * 2 + 8];
            bgl[0] = *(const unsigned*)&sGl[n * AST + tg * 2];
            bgl[1] = *(const unsigned*)&sGl[n * AST + tg * 2 + 8];
            buh[0] = *(const unsigned*)&sUh[n * AST + tg * 2];
            buh[1] = *(const unsigned*)&sUh[n * AST + tg * 2 + 8];
            bul[0] = *(const unsigned*)&sUl[n * AST + tg * 2];
            bul[1] = *(const unsigned*)&sUl[n * AST + tg * 2 + 8];
#pragma unroll
            for (int mi = 0; mi < 2; mi++) {
                mma_bf16(accg[mi][ni], ah[mi], bgh);
                mma_bf16(accg[mi][ni], ah[mi], bgl);
                mma_bf16(accg[mi][ni], al[mi], bgh);
                mma_bf16(accu[mi][ni], ah[mi], buh);
                mma_bf16(accu[mi][ni], ah[mi], bul);
                mma_bf16(accu[mi][ni], al[mi], buh);
            }
        }
    }

    // ---- epilogue: act = silu(gate)*up, split to bf16 hi/lo ----
#pragma unroll
    for (int mi = 0; mi < 2; mi++) {
#pragma unroll
        for (int h = 0; h < 2; h++) {
            int rl = mtile * BM + wm * 32 + mi * 16 + gid + h * 8;
            if (rl < cnt) {
                size_t rowoff = (size_t)(segbase + rl) * Dh;
#pragma unroll
                for (int ni = 0; ni < 8; ni++) {
                    int c = ntile * BN + wn * 64 + ni * 8 + tg * 2;
                    float g0 = accg[mi][ni][h * 2 + 0], g1 = accg[mi][ni][h * 2 + 1];
                    float u0 = accu[mi][ni][h * 2 + 0], u1 = accu[mi][ni][h * 2 + 1];
                    float a0 = g0 * u0 / (1.f + __expf(-g0));
                    float a1 = g1 * u1 / (1.f + __expf(-g1));
                    __nv_bfloat16 h0, l0, h1, l1;
                    split_bf16(a0, h0, l0); split_bf16(a1, h1, l1);
                    *(unsigned*)&g_act_hi[rowoff + c] = pk(h0, h1);
                    *(unsigned*)&g_act_lo[rowoff + c] = pk(l0, l1);
                }
            }
        }
    }
}

// ---------------- K2: y = act @ down_w^T ----------------
__global__ void __launch_bounds__(256) moe_k2(
    const float* __restrict__ down_w, const float* __restrict__ sdw)
{
    const int seg = blockIdx.z;
    const int cnt = (seg == NEXP) ? NTOK : g_counts[seg];
    const int mtile = blockIdx.y;
    if (mtile * BM >= cnt) return;
    const int ntile = blockIdx.x;
    const int segbase = (seg == NEXP) ? NASSIGN : g_offsets[seg];
    const float* dw = (seg == NEXP) ? sdw : down_w + (size_t)seg * Dh * Dh;

    __shared__ __align__(16) __nv_bfloat16 sAh[BM * AST], sAl[BM * AST];
    __shared__ __align__(16) __nv_bfloat16 sBh[BN * AST], sBl[BN * AST];

    const int tid = threadIdx.x;
    const int wid = tid >> 5, lane = tid & 31, gid = lane >> 2, tg = lane & 3;
    const int wm = wid >> 1, wn = wid & 1;

    float acc[2][8][4];
#pragma unroll
    for (int mi = 0; mi < 2; mi++)
#pragma unroll
        for (int ni = 0; ni < 8; ni++)
#pragma unroll
            for (int j = 0; j < 4; j++) acc[mi][ni][j] = 0.f;

    for (int k0 = 0; k0 < Dh; k0 += BK) {
        uint2 av[4];
#pragma unroll
        for (int i = 0; i < 4; i++) {
            int idx2 = tid + i * 256; int arr = idx2 >> 9; int rem = idx2 & 511;
            int row = rem >> 2; int c4 = rem & 3;
            int rl = mtile * BM + row;
            const __nv_bfloat16* src = arr ? g_act_lo : g_act_hi;
            av[i] = (rl < cnt) ? *(const uint2*)&src[(size_t)(segbase + rl) * Dh + k0 + c4 * 4]
                               : make_uint2(0u, 0u);
        }
        float4 bv[2];
#pragma unroll
        for (int i = 0; i < 2; i++) {
            int idx2 = tid + i * 256; int row = idx2 >> 2; int c4 = idx2 & 3;
            bv[i] = *(const float4*)(dw + (size_t)(ntile * BN + row) * Dh + k0 + c4 * 4);
        }
        __syncthreads();
#pragma unroll
        for (int i = 0; i < 4; i++) {
            int idx2 = tid + i * 256; int arr = idx2 >> 9; int rem = idx2 & 511;
            int row = rem >> 2; int c4 = rem & 3;
            __nv_bfloat16* dst = arr ? sAl : sAh;
            *(uint2*)&dst[row * AST + c4 * 4] = av[i];
        }
#pragma unroll
        for (int i = 0; i < 2; i++) {
            int idx2 = tid + i * 256; int row = idx2 >> 2; int c4 = idx2 & 3;
            __nv_bfloat16 h0, l0, h1, l1, h2, l2, h3, l3;
            split_bf16(bv[i].x, h0, l0); split_bf16(bv[i].y, h1, l1);
            split_bf16(bv[i].z, h2, l2); split_bf16(bv[i].w, h3, l3);
            *(uint2*)&sBh[row * AST + c4 * 4] = make_uint2(pk(h0, h1), pk(h2, h3));
            *(uint2*)&sBl[row * AST + c4 * 4] = make_uint2(pk(l0, l1), pk(l2, l3));
        }
        __syncthreads();

        unsigned ah[2][4], al[2][4];
#pragma unroll
        for (int mi = 0; mi < 2; mi++) {
            int mb = wm * 32 + mi * 16;
            int r0 = mb + gid, r1 = mb + gid + 8, kc = tg * 2;
            ah[mi][0] = *(const unsigned*)&sAh[r0 * AST + kc];
            ah[mi][1] = *(const unsigned*)&sAh[r1 * AST + kc];
            ah[mi][2] = *(const unsigned*)&sAh[r0 * AST + kc + 8];
            ah[mi][3] = *(const unsigned*)&sAh[r1 * AST + kc + 8];
            al[mi][0] = *(const unsigned*)&sAl[r0 * AST + kc];
            al[mi][1] = *(const unsigned*)&sAl[r1 * AST + kc];
            al[mi][2] = *(const unsigned*)&sAl[r0 * AST + kc + 8];
            al[mi][3] = *(const unsigned*)&sAl[r1 * AST + kc + 8];
        }
#pragma unroll
        for (int ni = 0; ni < 8; ni++) {
            int n = wn * 64 + ni * 8 + gid;
            unsigned bh[2], bl[2];
            bh[0] = *(const unsigned*)&sBh[n * AST + tg * 2];
            bh[1] = *(const unsigned*)&sBh[n * AST + tg * 2 + 8];
            bl[0] = *(const unsigned*)&sBl[n * AST + tg * 2];
            bl[1] = *(const unsigned*)&sBl[n * AST + tg * 2 + 8];
#pragma unroll
            for (int mi = 0; mi < 2; mi++) {
                mma_bf16(acc[mi][ni], ah[mi], bh);
                mma_bf16(acc[mi][ni], ah[mi], bl);
                mma_bf16(acc[mi][ni], al[mi], bh);
            }
        }
    }

#pragma unroll
    for (int mi = 0; mi < 2; mi++) {
#pragma unroll
        for (int h = 0; h < 2; h++) {
            int rl = mtile * BM + wm * 32 + mi * 16 + gid + h * 8;
            if (rl < cnt) {
                size_t rowoff = (size_t)(segbase + rl) * Dh;
#pragma unroll
                for (int ni = 0; ni < 8; ni++) {
                    int c = ntile * BN + wn * 64 + ni * 8 + tg * 2;
                    float2 v = make_float2(acc[mi][ni][h * 2 + 0], acc[mi][ni][h * 2 + 1]);
                    *(float2*)&g_ys[rowoff + c] = v;
                }
            }
        }
    }
}

// ---------------- combine: out = shared + w0*e0 + w1*e1 ----------------
__global__ void combine_kernel(const float* __restrict__ weights, float* __restrict__ out) {
    int idx = blockIdx.x * blockDim.x + threadIdx.x;
    if (idx >= NTOK * (Dh / 4)) return;
    int t = idx / (Dh / 4);
    int c4 = idx % (Dh / 4);
    float4 r = *(const float4*)&g_ys[(size_t)(NASSIGN + t) * Dh + c4 * 4];
    int p0 = g_slotmap[2 * t], p1 = g_slotmap[2 * t + 1];
    float w0 = weights[2 * t], w1 = weights[2 * t + 1];
    float4 y0 = *(const float4*)&g_ys[(size_t)p0 * Dh + c4 * 4];
    float4 y1 = *(const float4*)&g_ys[(size_t)p1 * Dh + c4 * 4];
    r.x += w0 * y0.x + w1 * y1.x;
    r.y += w0 * y0.y + w1 * y1.y;
    r.z += w0 * y0.z + w1 * y1.z;
    r.w += w0 * y0.w + w1 * y1.w;
    *(float4*)&out[(size_t)t * Dh + c4 * 4] = r;
}

extern "C" void kernel_launch(void* const* d_in, const int* in_sizes, int n_in,
                              void* d_out, int out_size) {
    const float* x        = (const float*)d_in[0];
    const float* weights  = (const float*)d_in[1];
    const int* idx        = (const int*)d_in[2];   // int32! (jax x64 disabled)
    // d_in[3], d_in[4]: expert_offsets / expert_token_counts (zeros, unused)
    const float* gate_w   = (const float*)d_in[5];
    const float* up_w     = (const float*)d_in[6];
    const float* down_w   = (const float*)d_in[7];
    const float* sgw      = (const float*)d_in[8];
    const float* suw      = (const float*)d_in[9];
    const float* sdw      = (const float*)d_in[10];
    float* out = (float*)d_out;

    route_zero_kernel<<<1, 32>>>();
    route_count_kernel<<<(NASSIGN + 255) / 256, 256>>>(idx);
    route_offsets_kernel<<<1, 1>>>();
    route_scatter_kernel<<<(NASSIGN + 255) / 256, 256>>>(idx);

    dim3 grid(Dh / BN, 32, NEXP + 1);  // (ntiles, max mtiles, segments incl shared)
    moe_k1<<<grid, 256>>>(x, gate_w, up_w, sgw, suw);
    moe_k2<<<grid, 256>>>(down_w, sdw);

    combine_kernel<<<(NTOK * (Dh / 4) + 255) / 256, 256>>>(weights, out);
}

// round 4
// speedup vs baseline: 1.1814x; 1.1814x over previous
#include <cuda_runtime.h>
#include <cuda_bf16.h>
#include <cstdint>

#define Dh   2048
#define SEQ  1024
#define GRP  2
#define NEXP 8
#define TOPK 2
#define NTOK (GRP*SEQ)          // 2048 tokens
#define NASSIGN (NTOK*TOPK)     // 4096 routed assignments
#define NSLOT (NASSIGN + NTOK)  // 6144 rows total (routed + shared)
#define BM 128
#define BN 128
#define BK 32
#define SST 40                  // smem row stride (elems); 80B, 16B-aligned rows, conflict-free frag LDS
#define TS (BM*SST)             // elems per tile (5120)

// ---------------- device scratch (static: no runtime allocation) ----------------
__device__ int g_counts[NEXP];
__device__ int g_offsets[NEXP];
__device__ int g_cursor[NEXP];
__device__ int g_rowmap[NASSIGN];    // slot -> token id
__device__ int g_slotmap[NASSIGN];   // assignment (t*2+k) -> slot
__device__ __align__(16) __nv_bfloat16 g_x_hi[(size_t)NTOK * Dh];
__device__ __align__(16) __nv_bfloat16 g_x_lo[(size_t)NTOK * Dh];
__device__ __align__(16) __nv_bfloat16 g_gate_hi[(size_t)NEXP * Dh * Dh];
__device__ __align__(16) __nv_bfloat16 g_gate_lo[(size_t)NEXP * Dh * Dh];
__device__ __align__(16) __nv_bfloat16 g_up_hi[(size_t)NEXP * Dh * Dh];
__device__ __align__(16) __nv_bfloat16 g_up_lo[(size_t)NEXP * Dh * Dh];
__device__ __align__(16) __nv_bfloat16 g_dn_hi[(size_t)NEXP * Dh * Dh];
__device__ __align__(16) __nv_bfloat16 g_dn_lo[(size_t)NEXP * Dh * Dh];
__device__ __align__(16) __nv_bfloat16 g_sg_hi[(size_t)Dh * Dh];
__device__ __align__(16) __nv_bfloat16 g_sg_lo[(size_t)Dh * Dh];
__device__ __align__(16) __nv_bfloat16 g_su_hi[(size_t)Dh * Dh];
__device__ __align__(16) __nv_bfloat16 g_su_lo[(size_t)Dh * Dh];
__device__ __align__(16) __nv_bfloat16 g_sd_hi[(size_t)Dh * Dh];
__device__ __align__(16) __nv_bfloat16 g_sd_lo[(size_t)Dh * Dh];
__device__ __align__(16) __nv_bfloat16 g_act_hi[(size_t)NSLOT * Dh];
__device__ __align__(16) __nv_bfloat16 g_act_lo[(size_t)NSLOT * Dh];
__device__ __align__(16) float g_ys[(size_t)NSLOT * Dh];

// ---------------- helpers ----------------
__device__ __forceinline__ unsigned pk(__nv_bfloat16 a, __nv_bfloat16 b) {
    return (unsigned)__bfloat16_as_ushort(a) | ((unsigned)__bfloat16_as_ushort(b) << 16);
}
__device__ __forceinline__ void split_bf16(float v, __nv_bfloat16& h, __nv_bfloat16& l) {
    h = __float2bfloat16(v);
    l = __float2bfloat16(v - __bfloat162float(h));
}
__device__ __forceinline__ void mma_bf16(float c[4], const unsigned a[4], const unsigned b[2]) {
    asm volatile(
        "mma.sync.aligned.m16n8k16.row.col.f32.bf16.bf16.f32 "
        "{%0,%1,%2,%3},{%4,%5,%6,%7},{%8,%9},{%0,%1,%2,%3};\n"
        : "+f"(c[0]), "+f"(c[1]), "+f"(c[2]), "+f"(c[3])
        : "r"(a[0]), "r"(a[1]), "r"(a[2]), "r"(a[3]), "r"(b[0]), "r"(b[1]));
}
__device__ __forceinline__ void cp16(__nv_bfloat16* dst, const __nv_bfloat16* src, bool p) {
    unsigned d = (unsigned)__cvta_generic_to_shared(dst);
    int sz = p ? 16 : 0;
    asm volatile("cp.async.cg.shared.global [%0], [%1], 16, %2;\n" :: "r"(d), "l"(src), "r"(sz));
}
#define CP_COMMIT() asm volatile("cp.async.commit_group;\n")
#define CP_WAIT0()  asm volatile("cp.async.wait_group 0;\n")

// ---------------- fp32 -> bf16 hi/lo conversion ----------------
__global__ void cvt_kernel(const float* __restrict__ src,
                           __nv_bfloat16* __restrict__ hi, __nv_bfloat16* __restrict__ lo,
                           int n4) {
    int i = blockIdx.x * blockDim.x + threadIdx.x;
    if (i >= n4) return;
    float4 v = ((const float4*)src)[i];
    __nv_bfloat16 h0, l0, h1, l1, h2, l2, h3, l3;
    split_bf16(v.x, h0, l0); split_bf16(v.y, h1, l1);
    split_bf16(v.z, h2, l2); split_bf16(v.w, h3, l3);
    ((uint2*)hi)[i] = make_uint2(pk(h0, h1), pk(h2, h3));
    ((uint2*)lo)[i] = make_uint2(pk(l0, l1), pk(l2, l3));
}

// ---------------- routing (indices arrive as int32) ----------------
__global__ void route_zero_kernel() {
    int t = threadIdx.x;
    if (t < NEXP) { g_counts[t] = 0; g_cursor[t] = 0; }
}
__global__ void route_count_kernel(const int* __restrict__ idx) {
    int i = blockIdx.x * blockDim.x + threadIdx.x;
    if (i < NASSIGN) {
        int e = idx[i];
        if (e >= 0 && e < NEXP) atomicAdd(&g_counts[e], 1);
    }
}
__global__ void route_offsets_kernel() {
    if (threadIdx.x == 0) {
        int acc = 0;
        for (int e = 0; e < NEXP; e++) { g_offsets[e] = acc; acc += g_counts[e]; }
    }
}
__global__ void route_scatter_kernel(const int* __restrict__ idx) {
    int i = blockIdx.x * blockDim.x + threadIdx.x;
    if (i < NASSIGN) {
        int e = idx[i];
        if (e < 0) e = 0;
        if (e >= NEXP) e = NEXP - 1;
        int pos = g_offsets[e] + atomicAdd(&g_cursor[e], 1);
        g_rowmap[pos] = i >> 1;   // token id (TOPK=2)
        g_slotmap[i] = pos;
    }
}

// ---------------- K1: gate/up GEMMs + SiLU -> act hi/lo ----------------
// dynamic smem: [stage(2)][mat(6): Ah Al Gh Gl Uh Ul] x TS elems = 122880 B
__global__ void __launch_bounds__(256) moe_k1() {
    const int seg = blockIdx.z;
    const int cnt = (seg == NEXP) ? NTOK : g_counts[seg];
    const int mtile = blockIdx.y;
    if (mtile * BM >= cnt) return;
    const int ntile = blockIdx.x;
    const int segbase = (seg == NEXP) ? NASSIGN : g_offsets[seg];

    const __nv_bfloat16 *gh, *gl, *uh, *ul;
    if (seg == NEXP) { gh = g_sg_hi; gl = g_sg_lo; uh = g_su_hi; ul = g_su_lo; }
    else {
        size_t off = (size_t)seg * Dh * Dh;
        gh = g_gate_hi + off; gl = g_gate_lo + off;
        uh = g_up_hi + off;   ul = g_up_lo + off;
    }

    extern __shared__ __align__(16) __nv_bfloat16 sm[];
    __shared__ int stok[BM];

    const int tid = threadIdx.x;
    if (tid < BM) {
        int r = mtile * BM + tid;
        stok[tid] = (r < cnt) ? ((seg == NEXP) ? r : g_rowmap[segbase + r]) : -1;
    }
    __syncthreads();

    const int wid = tid >> 5, lane = tid & 31, gid = lane >> 2, tg = lane & 3;
    const int wm = wid >> 1, wn = wid & 1;

    float accg[2][8][4], accu[2][8][4];
#pragma unroll
    for (int mi = 0; mi < 2; mi++)
#pragma unroll
        for (int ni = 0; ni < 8; ni++)
#pragma unroll
            for (int j = 0; j < 4; j++) { accg[mi][ni][j] = 0.f; accu[mi][ni][j] = 0.f; }

    // thread's fixed copy coords: 512 16B-chunks per tile, 2 per thread
    const int r0c = tid >> 2, c8a = (tid & 3);           // chunk set 0
    const int r1c = (tid + 256) >> 2, c8b = (tid & 3);   // chunk set 1 (rows 64..127)

    auto issue = [&](int st, int k0) {
        __nv_bfloat16* base = sm + st * 6 * TS;
        // A (x gathered by token), hi+lo
        {
            int tok0 = stok[r0c], tok1 = stok[r1c];
            bool p0 = tok0 >= 0, p1 = tok1 >= 0;
            size_t o0 = (size_t)(p0 ? tok0 : 0) * Dh + k0 + c8a * 8;
            size_t o1 = (size_t)(p1 ? tok1 : 0) * Dh + k0 + c8b * 8;
            cp16(base + 0 * TS + r0c * SST + c8a * 8, g_x_hi + o0, p0);
            cp16(base + 0 * TS + r1c * SST + c8b * 8, g_x_hi + o1, p1);
            cp16(base + 1 * TS + r0c * SST + c8a * 8, g_x_lo + o0, p0);
            cp16(base + 1 * TS + r1c * SST + c8b * 8, g_x_lo + o1, p1);
        }
        // B: gate hi/lo, up hi/lo
        {
            size_t o0 = (size_t)(ntile * BN + r0c) * Dh + k0 + c8a * 8;
            size_t o1 = (size_t)(ntile * BN + r1c) * Dh + k0 + c8b * 8;
            cp16(base + 2 * TS + r0c * SST + c8a * 8, gh + o0, true);
            cp16(base + 2 * TS + r1c * SST + c8b * 8, gh + o1, true);
            cp16(base + 3 * TS + r0c * SST + c8a * 8, gl + o0, true);
            cp16(base + 3 * TS + r1c * SST + c8b * 8, gl + o1, true);
            cp16(base + 4 * TS + r0c * SST + c8a * 8, uh + o0, true);
            cp16(base + 4 * TS + r1c * SST + c8b * 8, uh + o1, true);
            cp16(base + 5 * TS + r0c * SST + c8a * 8, ul + o0, true);
            cp16(base + 5 * TS + r1c * SST + c8b * 8, ul + o1, true);
        }
    };

    issue(0, 0);
    CP_COMMIT();
    int s = 0;
    for (int k0 = 0; k0 < Dh; k0 += BK, s ^= 1) {
        CP_WAIT0();
        __syncthreads();
        if (k0 + BK < Dh) { issue(s ^ 1, k0 + BK); CP_COMMIT(); }

        const __nv_bfloat16* Ah = sm + (s * 6 + 0) * TS;
        const __nv_bfloat16* Al = sm + (s * 6 + 1) * TS;
        const __nv_bfloat16* Gh = sm + (s * 6 + 2) * TS;
        const __nv_bfloat16* Gl = sm + (s * 6 + 3) * TS;
        const __nv_bfloat16* Uh = sm + (s * 6 + 4) * TS;
        const __nv_bfloat16* Ul = sm + (s * 6 + 5) * TS;

#pragma unroll
        for (int ks = 0; ks < 2; ks++) {
            const int kc = ks * 16 + tg * 2;
            unsigned ah[2][4], al[2][4];
#pragma unroll
            for (int mi = 0; mi < 2; mi++) {
                int ra = wm * 32 + mi * 16 + gid, rb = ra + 8;
                ah[mi][0] = *(const unsigned*)&Ah[ra * SST + kc];
                ah[mi][1] = *(const unsigned*)&Ah[rb * SST + kc];
                ah[mi][2] = *(const unsigned*)&Ah[ra * SST + kc + 8];
                ah[mi][3] = *(const unsigned*)&Ah[rb * SST + kc + 8];
                al[mi][0] = *(const unsigned*)&Al[ra * SST + kc];
                al[mi][1] = *(const unsigned*)&Al[rb * SST + kc];
                al[mi][2] = *(const unsigned*)&Al[ra * SST + kc + 8];
                al[mi][3] = *(const unsigned*)&Al[rb * SST + kc + 8];
            }
#pragma unroll
            for (int ni = 0; ni < 8; ni++) {
                int n = wn * 64 + ni * 8 + gid;
                unsigned bgh[2], bgl[2], buh[2], bul[2];
                bgh[0] = *(const unsigned*)&Gh[n * SST + kc];
                bgh[1] = *(const unsigned*)&Gh[n * SST + kc + 8];
                bgl[0] = *(const unsigned*)&Gl[n * SST + kc];
                bgl[1] = *(const unsigned*)&Gl[n * SST + kc + 8];
                buh[0] = *(const unsigned*)&Uh[n * SST + kc];
                buh[1] = *(const unsigned*)&Uh[n * SST + kc + 8];
                bul[0] = *(const unsigned*)&Ul[n * SST + kc];
                bul[1] = *(const unsigned*)&Ul[n * SST + kc + 8];
#pragma unroll
                for (int mi = 0; mi < 2; mi++) {
                    mma_bf16(accg[mi][ni], ah[mi], bgh);
                    mma_bf16(accg[mi][ni], ah[mi], bgl);
                    mma_bf16(accg[mi][ni], al[mi], bgh);
                    mma_bf16(accu[mi][ni], ah[mi], buh);
                    mma_bf16(accu[mi][ni], ah[mi], bul);
                    mma_bf16(accu[mi][ni], al[mi], buh);
                }
            }
        }
    }

    // epilogue: act = silu(gate)*up, split to bf16 hi/lo
#pragma unroll
    for (int mi = 0; mi < 2; mi++) {
#pragma unroll
        for (int h = 0; h < 2; h++) {
            int rl = mtile * BM + wm * 32 + mi * 16 + gid + h * 8;
            if (rl < cnt) {
                size_t rowoff = (size_t)(segbase + rl) * Dh;
#pragma unroll
                for (int ni = 0; ni < 8; ni++) {
                    int c = ntile * BN + wn * 64 + ni * 8 + tg * 2;
                    float g0 = accg[mi][ni][h * 2 + 0], g1 = accg[mi][ni][h * 2 + 1];
                    float u0 = accu[mi][ni][h * 2 + 0], u1 = accu[mi][ni][h * 2 + 1];
                    float a0 = g0 * u0 / (1.f + __expf(-g0));
                    float a1 = g1 * u1 / (1.f + __expf(-g1));
                    __nv_bfloat16 h0, l0, h1, l1;
                    split_bf16(a0, h0, l0); split_bf16(a1, h1, l1);
                    *(unsigned*)&g_act_hi[rowoff + c] = pk(h0, h1);
                    *(unsigned*)&g_act_lo[rowoff + c] = pk(l0, l1);
                }
            }
        }
    }
}

// ---------------- K2: y = act @ down_w^T ----------------
// dynamic smem: [stage(2)][mat(4): Ah Al Bh Bl] x TS = 81920 B
__global__ void __launch_bounds__(256) moe_k2() {
    const int seg = blockIdx.z;
    const int cnt = (seg == NEXP) ? NTOK : g_counts[seg];
    const int mtile = blockIdx.y;
    if (mtile * BM >= cnt) return;
    const int ntile = blockIdx.x;
    const int segbase = (seg == NEXP) ? NASSIGN : g_offsets[seg];

    const __nv_bfloat16 *dh, *dl;
    if (seg == NEXP) { dh = g_sd_hi; dl = g_sd_lo; }
    else { size_t off = (size_t)seg * Dh * Dh; dh = g_dn_hi + off; dl = g_dn_lo + off; }

    extern __shared__ __align__(16) __nv_bfloat16 sm[];

    const int tid = threadIdx.x;
    const int wid = tid >> 5, lane = tid & 31, gid = lane >> 2, tg = lane & 3;
    const int wm = wid >> 1, wn = wid & 1;

    float acc[2][8][4];
#pragma unroll
    for (int mi = 0; mi < 2; mi++)
#pragma unroll
        for (int ni = 0; ni < 8; ni++)
#pragma unroll
            for (int j = 0; j < 4; j++) acc[mi][ni][j] = 0.f;

    const int r0c = tid >> 2, c8a = (tid & 3);
    const int r1c = (tid + 256) >> 2, c8b = (tid & 3);

    auto issue = [&](int st, int k0) {
        __nv_bfloat16* base = sm + st * 4 * TS;
        {
            int ra = mtile * BM + r0c, rb = mtile * BM + r1c;
            bool p0 = ra < cnt, p1 = rb < cnt;
            size_t o0 = (size_t)(segbase + (p0 ? ra : 0)) * Dh + k0 + c8a * 8;
            size_t o1 = (size_t)(segbase + (p1 ? rb : 0)) * Dh + k0 + c8b * 8;
            cp16(base + 0 * TS + r0c * SST + c8a * 8, g_act_hi + o0, p0);
            cp16(base + 0 * TS + r1c * SST + c8b * 8, g_act_hi + o1, p1);
            cp16(base + 1 * TS + r0c * SST + c8a * 8, g_act_lo + o0, p0);
            cp16(base + 1 * TS + r1c * SST + c8b * 8, g_act_lo + o1, p1);
        }
        {
            size_t o0 = (size_t)(ntile * BN + r0c) * Dh + k0 + c8a * 8;
            size_t o1 = (size_t)(ntile * BN + r1c) * Dh + k0 + c8b * 8;
            cp16(base + 2 * TS + r0c * SST + c8a * 8, dh + o0, true);
            cp16(base + 2 * TS + r1c * SST + c8b * 8, dh + o1, true);
            cp16(base + 3 * TS + r0c * SST + c8a * 8, dl + o0, true);
            cp16(base + 3 * TS + r1c * SST + c8b * 8, dl + o1, true);
        }
    };

    issue(0, 0);
    CP_COMMIT();
    int s = 0;
    for (int k0 = 0; k0 < Dh; k0 += BK, s ^= 1) {
        CP_WAIT0();
        __syncthreads();
        if (k0 + BK < Dh) { issue(s ^ 1, k0 + BK); CP_COMMIT(); }

        const __nv_bfloat16* Ah = sm + (s * 4 + 0) * TS;
        const __nv_bfloat16* Al = sm + (s * 4 + 1) * TS;
        const __nv_bfloat16* Bh = sm + (s * 4 + 2) * TS;
        const __nv_bfloat16* Bl = sm + (s * 4 + 3) * TS;

#pragma unroll
        for (int ks = 0; ks < 2; ks++) {
            const int kc = ks * 16 + tg * 2;
            unsigned ah[2][4], al[2][4];
#pragma unroll
            for (int mi = 0; mi < 2; mi++) {
                int ra = wm * 32 + mi * 16 + gid, rb = ra + 8;
                ah[mi][0] = *(const unsigned*)&Ah[ra * SST + kc];
                ah[mi][1] = *(const unsigned*)&Ah[rb * SST + kc];
                ah[mi][2] = *(const unsigned*)&Ah[ra * SST + kc + 8];
                ah[mi][3] = *(const unsigned*)&Ah[rb * SST + kc + 8];
                al[mi][0] = *(const unsigned*)&Al[ra * SST + kc];
                al[mi][1] = *(const unsigned*)&Al[rb * SST + kc];
                al[mi][2] = *(const unsigned*)&Al[ra * SST + kc + 8];
                al[mi][3] = *(const unsigned*)&Al[rb * SST + kc + 8];
            }
#pragma unroll
            for (int ni = 0; ni < 8; ni++) {
                int n = wn * 64 + ni * 8 + gid;
                unsigned bh[2], bl[2];
                bh[0] = *(const unsigned*)&Bh[n * SST + kc];
                bh[1] = *(const unsigned*)&Bh[n * SST + kc + 8];
                bl[0] = *(const unsigned*)&Bl[n * SST + kc];
                bl[1] = *(const unsigned*)&Bl[n * SST + kc + 8];
#pragma unroll
                for (int mi = 0; mi < 2; mi++) {
                    mma_bf16(acc[mi][ni], ah[mi], bh);
                    mma_bf16(acc[mi][ni], ah[mi], bl);
                    mma_bf16(acc[mi][ni], al[mi], bh);
                }
            }
        }
    }

#pragma unroll
    for (int mi = 0; mi < 2; mi++) {
#pragma unroll
        for (int h = 0; h < 2; h++) {
            int rl = mtile * BM + wm * 32 + mi * 16 + gid + h * 8;
            if (rl < cnt) {
                size_t rowoff = (size_t)(segbase + rl) * Dh;
#pragma unroll
                for (int ni = 0; ni < 8; ni++) {
                    int c = ntile * BN + wn * 64 + ni * 8 + tg * 2;
                    float2 v = make_float2(acc[mi][ni][h * 2 + 0], acc[mi][ni][h * 2 + 1]);
                    *(float2*)&g_ys[rowoff + c] = v;
                }
            }
        }
    }
}

// ---------------- combine: out = shared + w0*e0 + w1*e1 ----------------
__global__ void combine_kernel(const float* __restrict__ weights, float* __restrict__ out) {
    int idx = blockIdx.x * blockDim.x + threadIdx.x;
    if (idx >= NTOK * (Dh / 4)) return;
    int t = idx / (Dh / 4);
    int c4 = idx % (Dh / 4);
    float4 r = *(const float4*)&g_ys[(size_t)(NASSIGN + t) * Dh + c4 * 4];
    int p0 = g_slotmap[2 * t], p1 = g_slotmap[2 * t + 1];
    float w0 = weights[2 * t], w1 = weights[2 * t + 1];
    float4 y0 = *(const float4*)&g_ys[(size_t)p0 * Dh + c4 * 4];
    float4 y1 = *(const float4*)&g_ys[(size_t)p1 * Dh + c4 * 4];
    r.x += w0 * y0.x + w1 * y1.x;
    r.y += w0 * y0.y + w1 * y1.y;
    r.z += w0 * y0.z + w1 * y1.z;
    r.w += w0 * y0.w + w1 * y1.w;
    *(float4*)&out[(size_t)t * Dh + c4 * 4] = r;
}

extern "C" void kernel_launch(void* const* d_in, const int* in_sizes, int n_in,
                              void* d_out, int out_size) {
    const float* x        = (const float*)d_in[0];
    const float* weights  = (const float*)d_in[1];
    const int* idx        = (const int*)d_in[2];   // int32 (jax x64 disabled)
    const float* gate_w   = (const float*)d_in[5];
    const float* up_w     = (const float*)d_in[6];
    const float* down_w   = (const float*)d_in[7];
    const float* sgw      = (const float*)d_in[8];
    const float* suw      = (const float*)d_in[9];
    const float* sdw      = (const float*)d_in[10];
    float* out = (float*)d_out;

    static bool attr_done = false;
    if (!attr_done) {
        cudaFuncSetAttribute(moe_k1, cudaFuncAttributeMaxDynamicSharedMemorySize, 2 * 6 * TS * 2);
        cudaFuncSetAttribute(moe_k2, cudaFuncAttributeMaxDynamicSharedMemorySize, 2 * 4 * TS * 2);
        attr_done = true;
    }

    // precision-split conversion (hi/lo bf16)
    {
        __nv_bfloat16 *xh, *xl, *gh, *gl, *uh, *ul, *dnh, *dnl, *sgh, *sgl, *suh, *sul, *sdh, *sdl;
        cudaGetSymbolAddress((void**)&xh, g_x_hi);   cudaGetSymbolAddress((void**)&xl, g_x_lo);
        cudaGetSymbolAddress((void**)&gh, g_gate_hi); cudaGetSymbolAddress((void**)&gl, g_gate_lo);
        cudaGetSymbolAddress((void**)&uh, g_up_hi);   cudaGetSymbolAddress((void**)&ul, g_up_lo);
        cudaGetSymbolAddress((void**)&dnh, g_dn_hi);  cudaGetSymbolAddress((void**)&dnl, g_dn_lo);
        cudaGetSymbolAddress((void**)&sgh, g_sg_hi);  cudaGetSymbolAddress((void**)&sgl, g_sg_lo);
        cudaGetSymbolAddress((void**)&suh, g_su_hi);  cudaGetSymbolAddress((void**)&sul, g_su_lo);
        cudaGetSymbolAddress((void**)&sdh, g_sd_hi);  cudaGetSymbolAddress((void**)&sdl, g_sd_lo);

        int n4x = NTOK * Dh / 4;                 // 1M
        int n4e = NEXP * Dh * Dh / 4;            // 8M
        int n4s = Dh * Dh / 4;                   // 1M
        cvt_kernel<<<(n4x + 255) / 256, 256>>>(x, xh, xl, n4x);
        cvt_kernel<<<(n4e + 255) / 256, 256>>>(gate_w, gh, gl, n4e);
        cvt_kernel<<<(n4e + 255) / 256, 256>>>(up_w, uh, ul, n4e);
        cvt_kernel<<<(n4e + 255) / 256, 256>>>(down_w, dnh, dnl, n4e);
        cvt_kernel<<<(n4s + 255) / 256, 256>>>(sgw, sgh, sgl, n4s);
        cvt_kernel<<<(n4s + 255) / 256, 256>>>(suw, suh, sul, n4s);
        cvt_kernel<<<(n4s + 255) / 256, 256>>>(sdw, sdh, sdl, n4s);
    }

    route_zero_kernel<<<1, 32>>>();
    route_count_kernel<<<(NASSIGN + 255) / 256, 256>>>(idx);
    route_offsets_kernel<<<1, 1>>>();
    route_scatter_kernel<<<(NASSIGN + 255) / 256, 256>>>(idx);

    dim3 grid(Dh / BN, 32, NEXP + 1);  // (ntiles, max mtiles, segments incl shared)
    moe_k1<<<grid, 256, 2 * 6 * TS * 2>>>();
    moe_k2<<<grid, 256, 2 * 4 * TS * 2>>>();

    combine_kernel<<<(NTOK * (Dh / 4) + 255) / 256, 256>>>(weights, out);
}